// round 3
// baseline (speedup 1.0000x reference)
#include <cuda_runtime.h>
#include <cstdint>

// ---------------------------------------------------------------------------
// DynamicFixedQuantizer, R3:
//  - count_decide (primary, 296 blocks = 2 CTA/SM) computes sigma.
//  - quantize (secondary, PDL) overlaps its threefry RNG with the count pass,
//    then cudaGridDependencySynchronize() before reading sigma.
//  - 6 of 20 threefry rotations moved to the fma pipe via mul.wide.u32 with
//    the round XOR fused into a single LOP3 ((lo|hi)^x0, LUT 0x56).
// ---------------------------------------------------------------------------

__device__ unsigned int g_over  = 0u;
__device__ unsigned int g_under = 0u;
__device__ unsigned int g_done  = 0u;
__device__ float4 g_qp;   // x=sigma, y=1/sigma, z=tmin, w=tmax

// Thresholds from sigma0 = 2^(6-8) = 0.25, bit=8, half=128:
#define T_MAX0   31.75f
#define T_MIN0  (-32.0f)
#define HT_MAX0  15.875f
#define HT_MIN0 (-16.0f)

__device__ __forceinline__ void count4(float4 v, int& over, int& under) {
    over  += (v.x > T_MAX0)  + (v.x < T_MIN0);
    under += (v.x > HT_MAX0) + (v.x < HT_MIN0);
    over  += (v.y > T_MAX0)  + (v.y < T_MIN0);
    under += (v.y > HT_MAX0) + (v.y < HT_MIN0);
    over  += (v.z > T_MAX0)  + (v.z < T_MIN0);
    under += (v.z > HT_MAX0) + (v.z < HT_MIN0);
    over  += (v.w > T_MAX0)  + (v.w < T_MIN0);
    under += (v.w > HT_MAX0) + (v.w < HT_MIN0);
}

// Primary kernel: grid-stride count, block reduce, global atomics; the LAST
// block computes sigma/inv/tmin/tmax into g_qp and resets the accumulators
// (replay-deterministic under CUDA graph). PDL trigger = block exit.
__global__ void __launch_bounds__(256) count_decide_kernel(
        const float4* __restrict__ x4, int nquads, float n) {
    int tid    = blockIdx.x * blockDim.x + threadIdx.x;
    int stride = gridDim.x * blockDim.x;
    int over = 0, under = 0;

    int i = tid;
    for (; i + 3 * stride < nquads; i += 4 * stride) {
        float4 a = x4[i];
        float4 b = x4[i + stride];
        float4 c = x4[i + 2 * stride];
        float4 d = x4[i + 3 * stride];
        count4(a, over, under);
        count4(b, over, under);
        count4(c, over, under);
        count4(d, over, under);
    }
    for (; i < nquads; i += stride) {
        count4(x4[i], over, under);
    }

    over  = __reduce_add_sync(0xffffffffu, over);
    under = __reduce_add_sync(0xffffffffu, under);

    __shared__ int so[8], su[8];
    int warp = threadIdx.x >> 5;
    int lane = threadIdx.x & 31;
    if (lane == 0) { so[warp] = over; su[warp] = under; }
    __syncthreads();

    if (threadIdx.x == 0) {
        int o = 0, u = 0;
#pragma unroll
        for (int w = 0; w < 8; w++) { o += so[w]; u += su[w]; }
        atomicAdd(&g_over,  (unsigned)o);
        atomicAdd(&g_under, (unsigned)u);
        __threadfence();
        unsigned t = atomicAdd(&g_done, 1u);
        if (t == gridDim.x - 1) {
            unsigned ov = atomicAdd(&g_over,  0u);
            unsigned un = atomicAdd(&g_under, 0u);
            float overflow  = __uint2float_rn(ov) / n;
            float underflow = __uint2float_rn(un) / n;
            float sigma = 0.25f;
            if (overflow > 0.01f)       sigma = 0.5f;
            else if (underflow < 0.01f) sigma = 0.125f;
            g_qp = make_float4(sigma, 1.0f / sigma,
                               -(sigma * 128.0f), sigma * 128.0f - sigma);
            atomicExch(&g_over,  0u);
            atomicExch(&g_under, 0u);
            __threadfence();
            atomicExch(&g_done,  0u);
        }
    }
}

// --- integer add forced onto the fma pipe: IMAD d = a*one + b ---------------
__device__ __forceinline__ uint32_t addi(uint32_t a, uint32_t one, uint32_t b) {
    uint32_t d;
    asm("mad.lo.u32 %0, %1, %2, %3;" : "=r"(d) : "r"(a), "r"(one), "r"(b));
    return d;
}

// (lo | hi) ^ x0 in one LOP3 (LUT: (0xF0|0xCC)^0xAA = 0x56)
__device__ __forceinline__ uint32_t lop3_56(uint32_t a, uint32_t b, uint32_t c) {
    uint32_t d;
    asm("lop3.b32 %0, %1, %2, %3, 0x56;" : "=r"(d) : "r"(a), "r"(b), "r"(c));
    return d;
}

__global__ void __launch_bounds__(256) quantize_kernel(const float* __restrict__ x,
                                                       float* __restrict__ out,
                                                       uint32_t k0, uint32_t k1,
                                                       uint32_t one, int n) {
    int t = blockIdx.x * blockDim.x + threadIdx.x;
    int j = t << 2;
    if (j >= n) return;

    const uint32_t ks2 = k0 ^ k1 ^ 0x1BD11BDAu;
    const uint32_t kc1 = ks2 + 1u;
    const uint32_t kc2 = k0  + 2u;
    const uint32_t kc3 = k1  + 3u;
    const uint32_t kc4 = ks2 + 4u;
    const uint32_t kc5 = k0  + 5u;
    // rotation multipliers for the mul.wide form (hoisted, 2 regs)
    const uint32_t m13 = one << 13;
    const uint32_t m26 = one << 26;

    // Independent of sigma: load input + compute all 4 uniforms first so this
    // work overlaps the count kernel under programmatic dependent launch.
    float4 v = *reinterpret_cast<const float4*>(x + j);
    uint32_t x1b = addi((uint32_t)j, one, k1);   // j + k1
    float f[4];

    // SHF-form round: add (fma/IMAD), rotate (alu/SHF), xor (alu/LOP3)
#define TF_S(r) { x0 = addi(x0, one, x1); x1 = __funnelshift_l(x1, x1, (r)) ^ x0; }
    // wide-mul-form round: add (fma), rot as v*2^r (fma/IMAD.WIDE),
    // (lo|hi)^x0 fused into one LOP3 (alu)
#define TF_W(m) { x0 = addi(x0, one, x1);                                        \
                  uint64_t w;                                                    \
                  asm("mul.wide.u32 %0, %1, %2;" : "=l"(w) : "r"(x1), "r"(m));   \
                  x1 = lop3_56((uint32_t)w, (uint32_t)(w >> 32), x0); }

#pragma unroll
    for (int c = 0; c < 4; c++) {
        // threefry2x32 block: key=(k0,k1), counter=(0, j+c)
        uint32_t x0 = k0;
        uint32_t x1 = x1b + (uint32_t)c;
        // group 0 (rot 13,15,26,6) — wide at 13, 26
        TF_W(m13) TF_S(15) TF_W(m26) TF_S(6)
        x0 = addi(x0, one, k1);  x1 = addi(x1, one, kc1);
        // group 1 (rot 17,29,16,24)
        TF_S(17) TF_S(29) TF_S(16) TF_S(24)
        x0 = addi(x0, one, ks2); x1 = addi(x1, one, kc2);
        // group 2 (rot 13,15,26,6) — wide at 13, 26
        TF_W(m13) TF_S(15) TF_W(m26) TF_S(6)
        x0 = addi(x0, one, k0);  x1 = addi(x1, one, kc3);
        // group 3 (rot 17,29,16,24)
        TF_S(17) TF_S(29) TF_S(16) TF_S(24)
        x0 = addi(x0, one, k1);  x1 = addi(x1, one, kc4);
        // group 4 (rot 13,15,26,6) — wide at 13, 26
        TF_W(m13) TF_S(15) TF_W(m26) TF_S(6)
        x0 = addi(x0, one, ks2); x1 = addi(x1, one, kc5);

        uint32_t bits = x0 ^ x1;
        // f = float(bits>>9); exact (23-bit mantissa)
        f[c] = __uint2float_rn(bits >> 9);
    }
#undef TF_S
#undef TF_W

    // Wait for the count kernel's results (PDL dependency), then finish.
    cudaGridDependencySynchronize();
    float4 qp = g_qp;             // x=sigma, y=inv, z=tmin, w=tmax

    float4 q;
#pragma unroll
    for (int c = 0; c < 4; c++) {
        float a = (&v.x)[c];
        // s = a*inv + f*2^-23  (FFMA; bit-identical to FADD(a*inv, f*2^-23)
        // since f*2^-23 is exact). floor, scale, clip.
        float s  = __fmaf_rn(f[c], 1.1920928955078125e-7f, __fmul_rn(a, qp.y));
        float qv = __fmul_rn(floorf(s), qp.x);
        (&q.x)[c] = fminf(fmaxf(qv, qp.z), qp.w);
    }
    *reinterpret_cast<float4*>(out + j) = q;
}

// --- host-side threefry for key fold ---------------------------------------
static void h_threefry(uint32_t k0, uint32_t k1, uint32_t x0, uint32_t x1,
                       uint32_t& o0, uint32_t& o1) {
    auto rotl = [](uint32_t v, int r) { return (v << r) | (v >> (32 - r)); };
    uint32_t ks[3] = { k0, k1, k0 ^ k1 ^ 0x1BD11BDAu };
    const int R[2][4] = { {13, 15, 26, 6}, {17, 29, 16, 24} };
    x0 += ks[0]; x1 += ks[1];
    for (int i = 0; i < 5; i++) {
        for (int jj = 0; jj < 4; jj++) {
            x0 += x1; x1 = rotl(x1, R[i % 2][jj]); x1 ^= x0;
        }
        x0 += ks[(i + 1) % 3];
        x1 += ks[(i + 2) % 3] + (uint32_t)(i + 1);
    }
    o0 = x0; o1 = x1;
}

extern "C" void kernel_launch(void* const* d_in, const int* in_sizes, int n_in,
                              void* d_out, int out_size) {
    const float* x = (const float*)d_in[0];
    float* out = (float*)d_out;
    int n = in_sizes[0];           // 32*2048*2048 = 134217728

    // key = fold_in(key(42), 0): threefry_2x32(key=[0,42], count=[0,0])
    uint32_t fk0, fk1;
    h_threefry(0u, 42u, 0u, 0u, fk0, fk1);

    int nquads = n >> 2;
    // Primary: 2 CTAs/SM (296 blocks) — one wave, leaves SM slots free so the
    // PDL secondary's RNG work overlaps the count's memory phase.
    count_decide_kernel<<<296, 256>>>((const float4*)x, nquads, (float)n);

    // Secondary: programmatic dependent launch.
    int qthreads = (n + 3) >> 2;
    int qblocks = (qthreads + 255) / 256;

    cudaLaunchConfig_t cfg = {};
    cfg.gridDim  = dim3((unsigned)qblocks);
    cfg.blockDim = dim3(256);
    cfg.dynamicSmemBytes = 0;
    cfg.stream = 0;
    cudaLaunchAttribute attr[1];
    attr[0].id = cudaLaunchAttributeProgrammaticStreamSerialization;
    attr[0].val.programmaticStreamSerializationAllowed = 1;
    cfg.attrs = attr;
    cfg.numAttrs = 1;
    cudaLaunchKernelEx(&cfg, quantize_kernel, x, out, fk0, fk1, 1u, n);
}

// round 4
// speedup vs baseline: 1.0541x; 1.0541x over previous
#include <cuda_runtime.h>
#include <cstdint>

// ---------------------------------------------------------------------------
// DynamicFixedQuantizer, R4 (base = R2 structure, no PDL):
//  - count_decide fused kernel (2048 blocks) -> g_qp.
//  - quantize: threefry with 4/20 rounds in narrow IMAD+IMAD.HI form to
//    balance alu/fma pipes; clamp+floor fused into cvt.rmi.s8.f32 (saturating
//    round-to-neg-inf), removing both FMNMX from the alu pipe.
// ---------------------------------------------------------------------------

__device__ unsigned int g_over  = 0u;
__device__ unsigned int g_under = 0u;
__device__ unsigned int g_done  = 0u;
__device__ float4 g_qp;   // x=sigma, y=1/sigma, z=unused, w=unused

// Thresholds from sigma0 = 2^(6-8) = 0.25, bit=8, half=128:
#define T_MAX0   31.75f
#define T_MIN0  (-32.0f)
#define HT_MAX0  15.875f
#define HT_MIN0 (-16.0f)

__device__ __forceinline__ void count4(float4 v, int& over, int& under) {
    over  += (v.x > T_MAX0)  + (v.x < T_MIN0);
    under += (v.x > HT_MAX0) + (v.x < HT_MIN0);
    over  += (v.y > T_MAX0)  + (v.y < T_MIN0);
    under += (v.y > HT_MAX0) + (v.y < HT_MIN0);
    over  += (v.z > T_MAX0)  + (v.z < T_MIN0);
    under += (v.z > HT_MAX0) + (v.z < HT_MIN0);
    over  += (v.w > T_MAX0)  + (v.w < T_MIN0);
    under += (v.w > HT_MAX0) + (v.w < HT_MIN0);
}

__global__ void __launch_bounds__(256) count_decide_kernel(
        const float4* __restrict__ x4, int nquads, float n) {
    int tid    = blockIdx.x * blockDim.x + threadIdx.x;
    int stride = gridDim.x * blockDim.x;
    int over = 0, under = 0;

    int i = tid;
    for (; i + 3 * stride < nquads; i += 4 * stride) {
        float4 a = x4[i];
        float4 b = x4[i + stride];
        float4 c = x4[i + 2 * stride];
        float4 d = x4[i + 3 * stride];
        count4(a, over, under);
        count4(b, over, under);
        count4(c, over, under);
        count4(d, over, under);
    }
    for (; i < nquads; i += stride) {
        count4(x4[i], over, under);
    }

    over  = __reduce_add_sync(0xffffffffu, over);
    under = __reduce_add_sync(0xffffffffu, under);

    __shared__ int so[8], su[8];
    int warp = threadIdx.x >> 5;
    int lane = threadIdx.x & 31;
    if (lane == 0) { so[warp] = over; su[warp] = under; }
    __syncthreads();

    if (threadIdx.x == 0) {
        int o = 0, u = 0;
#pragma unroll
        for (int w = 0; w < 8; w++) { o += so[w]; u += su[w]; }
        atomicAdd(&g_over,  (unsigned)o);
        atomicAdd(&g_under, (unsigned)u);
        __threadfence();
        unsigned t = atomicAdd(&g_done, 1u);
        if (t == gridDim.x - 1) {
            unsigned ov = atomicAdd(&g_over,  0u);
            unsigned un = atomicAdd(&g_under, 0u);
            float overflow  = __uint2float_rn(ov) / n;
            float underflow = __uint2float_rn(un) / n;
            float sigma = 0.25f;
            if (overflow > 0.01f)       sigma = 0.5f;
            else if (underflow < 0.01f) sigma = 0.125f;
            g_qp = make_float4(sigma, 1.0f / sigma, 0.0f, 0.0f);
            atomicExch(&g_over,  0u);
            atomicExch(&g_under, 0u);
            __threadfence();
            atomicExch(&g_done,  0u);
        }
    }
}

// --- integer add forced onto the fma pipe: IMAD d = a*one + b ---------------
__device__ __forceinline__ uint32_t addi(uint32_t a, uint32_t one, uint32_t b) {
    uint32_t d;
    asm("mad.lo.u32 %0, %1, %2, %3;" : "=r"(d) : "r"(a), "r"(one), "r"(b));
    return d;
}

// (lo | hi) ^ x0 in one LOP3 (LUT: (0xF0|0xCC)^0xAA = 0x56)
__device__ __forceinline__ uint32_t lop3_56(uint32_t a, uint32_t b, uint32_t c) {
    uint32_t d;
    asm("lop3.b32 %0, %1, %2, %3, 0x56;" : "=r"(d) : "r"(a), "r"(b), "r"(c));
    return d;
}

// clip(floor(s), -128, 127) in one saturating round-to-neg-inf conversion,
// then back to float: replaces FRND + 2x FMNMX. Bit-identical because sigma>0
// is a power of two, t_min = -128*sigma, t_max = 127*sigma, and multiples of
// sigma in this range are exact floats.
__device__ __forceinline__ float floor_clip_s8(float s) {
    int   q;
    float r;
    asm("cvt.rmi.s8.f32 %0, %1;" : "=r"(q) : "f"(s));
    asm("cvt.rn.f32.s8 %0, %1;"  : "=f"(r) : "r"(q));
    return r;
}

__global__ void __launch_bounds__(256) quantize_kernel(const float* __restrict__ x,
                                                       float* __restrict__ out,
                                                       uint32_t k0, uint32_t k1,
                                                       uint32_t one, int n) {
    int t = blockIdx.x * blockDim.x + threadIdx.x;
    int j = t << 2;
    if (j >= n) return;

    const uint32_t ks2 = k0 ^ k1 ^ 0x1BD11BDAu;
    const uint32_t kc1 = ks2 + 1u;
    const uint32_t kc2 = k0  + 2u;
    const uint32_t kc3 = k1  + 3u;
    const uint32_t kc4 = ks2 + 4u;
    const uint32_t kc5 = k0  + 5u;
    // opaque rotate multipliers (runtime 'one' defeats constant folding so the
    // HI-form rounds stay IMAD/IMAD.HI on the fma pipe)
    const uint32_t m13 = one << 13;
    const uint32_t m26 = one << 26;

    float4 qp = g_qp;             // x=sigma, y=inv
    float4 v = *reinterpret_cast<const float4*>(x + j);
    float4 q;

    uint32_t x1b = addi((uint32_t)j, one, k1);   // j + k1

    // SHF-form round: IMAD (fma) + SHF rotate (alu) + LOP3 xor (alu)
#define TF_S(r) { x0 = addi(x0, one, x1); x1 = __funnelshift_l(x1, x1, (r)) ^ x0; }
    // HI-form round: IMAD add (fma) + mul.lo (fma) + mul.hi (fma) + fused
    // (lo|hi)^x0 LOP3 (alu). rotl(v,r) == (v*2^r)lo | mulhi(v,2^r).
#define TF_H(m) { x0 = addi(x0, one, x1);                                    \
                  uint32_t lo, hi;                                           \
                  asm("mul.lo.u32 %0, %2, %3;\n\t"                           \
                      "mul.hi.u32 %1, %2, %3;"                               \
                      : "=r"(lo), "=r"(hi) : "r"(x1), "r"(m));               \
                  x1 = lop3_56(lo, hi, x0); }

#pragma unroll
    for (int c = 0; c < 4; c++) {
        // threefry2x32 block: key=(k0,k1), counter=(0, j+c)
        uint32_t x0 = k0;
        uint32_t x1 = x1b + (uint32_t)c;
        // group 0 (13,15,26,6): HI-form at 13 and 26
        TF_H(m13) TF_S(15) TF_H(m26) TF_S(6)
        x0 = addi(x0, one, k1);  x1 = addi(x1, one, kc1);
        // group 1 (17,29,16,24)
        TF_S(17) TF_S(29) TF_S(16) TF_S(24)
        x0 = addi(x0, one, ks2); x1 = addi(x1, one, kc2);
        // group 2 (13,15,26,6): HI-form at 13 and 26
        TF_H(m13) TF_S(15) TF_H(m26) TF_S(6)
        x0 = addi(x0, one, k0);  x1 = addi(x1, one, kc3);
        // group 3 (17,29,16,24)
        TF_S(17) TF_S(29) TF_S(16) TF_S(24)
        x0 = addi(x0, one, k1);  x1 = addi(x1, one, kc4);
        // group 4 (13,15,26,6): all SHF (k=4 total HI rounds)
        TF_S(13) TF_S(15) TF_S(26) TF_S(6)
        x0 = addi(x0, one, ks2); x1 = addi(x1, one, kc5);

        uint32_t bits = x0 ^ x1;
        // u = float(bits>>9)*2^-23 == bitcast((bits>>9)|0x3f800000)-1 exactly.
        float f = __uint2float_rn(bits >> 9);
        float a = (&v.x)[c];
        // s = a*inv + u (FFMA, bit-identical: u term is exact).
        float s  = __fmaf_rn(f, 1.1920928955078125e-7f, __fmul_rn(a, qp.y));
        // clip(floor(s),-128,127)*sigma == clip(floor(s)*sigma, tmin, tmax)
        (&q.x)[c] = __fmul_rn(floor_clip_s8(s), qp.x);
    }
#undef TF_S
#undef TF_H

    *reinterpret_cast<float4*>(out + j) = q;
}

// --- host-side threefry for key fold ---------------------------------------
static void h_threefry(uint32_t k0, uint32_t k1, uint32_t x0, uint32_t x1,
                       uint32_t& o0, uint32_t& o1) {
    auto rotl = [](uint32_t v, int r) { return (v << r) | (v >> (32 - r)); };
    uint32_t ks[3] = { k0, k1, k0 ^ k1 ^ 0x1BD11BDAu };
    const int R[2][4] = { {13, 15, 26, 6}, {17, 29, 16, 24} };
    x0 += ks[0]; x1 += ks[1];
    for (int i = 0; i < 5; i++) {
        for (int jj = 0; jj < 4; jj++) {
            x0 += x1; x1 = rotl(x1, R[i % 2][jj]); x1 ^= x0;
        }
        x0 += ks[(i + 1) % 3];
        x1 += ks[(i + 2) % 3] + (uint32_t)(i + 1);
    }
    o0 = x0; o1 = x1;
}

extern "C" void kernel_launch(void* const* d_in, const int* in_sizes, int n_in,
                              void* d_out, int out_size) {
    const float* x = (const float*)d_in[0];
    float* out = (float*)d_out;
    int n = in_sizes[0];           // 32*2048*2048 = 134217728

    // key = fold_in(key(42), 0): threefry_2x32(key=[0,42], count=[0,0])
    uint32_t fk0, fk1;
    h_threefry(0u, 42u, 0u, 0u, fk0, fk1);

    int nquads = n >> 2;
    count_decide_kernel<<<2048, 256>>>((const float4*)x, nquads, (float)n);

    int qthreads = (n + 3) >> 2;
    int qblocks = (qthreads + 255) / 256;
    quantize_kernel<<<qblocks, 256>>>(x, out, fk0, fk1, 1u, n);
}

// round 5
// speedup vs baseline: 1.0905x; 1.0345x over previous
#include <cuda_runtime.h>
#include <cstdint>

// ---------------------------------------------------------------------------
// DynamicFixedQuantizer, R5 (= R2 threefry + R4 epilogue):
//  - count_decide fused kernel (2048 blocks) -> g_qp.
//  - quantize: all 20 rounds in IMAD(add)/SHF/LOP3 form (proven fastest);
//    floor+clamp fused into cvt.rmi.s8.f32; u-term fused into FFMA;
//    bits>>9 done as mulhi(bits, 2^23) on the fma pipe.
// ---------------------------------------------------------------------------

__device__ unsigned int g_over  = 0u;
__device__ unsigned int g_under = 0u;
__device__ unsigned int g_done  = 0u;
__device__ float4 g_qp;   // x=sigma, y=1/sigma

// Thresholds from sigma0 = 2^(6-8) = 0.25, bit=8, half=128:
#define T_MAX0   31.75f
#define T_MIN0  (-32.0f)
#define HT_MAX0  15.875f
#define HT_MIN0 (-16.0f)

__device__ __forceinline__ void count4(float4 v, int& over, int& under) {
    over  += (v.x > T_MAX0)  + (v.x < T_MIN0);
    under += (v.x > HT_MAX0) + (v.x < HT_MIN0);
    over  += (v.y > T_MAX0)  + (v.y < T_MIN0);
    under += (v.y > HT_MAX0) + (v.y < HT_MIN0);
    over  += (v.z > T_MAX0)  + (v.z < T_MIN0);
    under += (v.z > HT_MAX0) + (v.z < HT_MIN0);
    over  += (v.w > T_MAX0)  + (v.w < T_MIN0);
    under += (v.w > HT_MAX0) + (v.w < HT_MIN0);
}

__global__ void __launch_bounds__(256) count_decide_kernel(
        const float4* __restrict__ x4, int nquads, float n) {
    int tid    = blockIdx.x * blockDim.x + threadIdx.x;
    int stride = gridDim.x * blockDim.x;
    int over = 0, under = 0;

    int i = tid;
    for (; i + 3 * stride < nquads; i += 4 * stride) {
        float4 a = x4[i];
        float4 b = x4[i + stride];
        float4 c = x4[i + 2 * stride];
        float4 d = x4[i + 3 * stride];
        count4(a, over, under);
        count4(b, over, under);
        count4(c, over, under);
        count4(d, over, under);
    }
    for (; i < nquads; i += stride) {
        count4(x4[i], over, under);
    }

    over  = __reduce_add_sync(0xffffffffu, over);
    under = __reduce_add_sync(0xffffffffu, under);

    __shared__ int so[8], su[8];
    int warp = threadIdx.x >> 5;
    int lane = threadIdx.x & 31;
    if (lane == 0) { so[warp] = over; su[warp] = under; }
    __syncthreads();

    if (threadIdx.x == 0) {
        int o = 0, u = 0;
#pragma unroll
        for (int w = 0; w < 8; w++) { o += so[w]; u += su[w]; }
        atomicAdd(&g_over,  (unsigned)o);
        atomicAdd(&g_under, (unsigned)u);
        __threadfence();
        unsigned t = atomicAdd(&g_done, 1u);
        if (t == gridDim.x - 1) {
            unsigned ov = atomicAdd(&g_over,  0u);
            unsigned un = atomicAdd(&g_under, 0u);
            float overflow  = __uint2float_rn(ov) / n;
            float underflow = __uint2float_rn(un) / n;
            float sigma = 0.25f;
            if (overflow > 0.01f)       sigma = 0.5f;
            else if (underflow < 0.01f) sigma = 0.125f;
            g_qp = make_float4(sigma, 1.0f / sigma, 0.0f, 0.0f);
            atomicExch(&g_over,  0u);
            atomicExch(&g_under, 0u);
            __threadfence();
            atomicExch(&g_done,  0u);
        }
    }
}

// --- integer add forced onto the fma pipe: IMAD d = a*one + b ---------------
__device__ __forceinline__ uint32_t addi(uint32_t a, uint32_t one, uint32_t b) {
    uint32_t d;
    asm("mad.lo.u32 %0, %1, %2, %3;" : "=r"(d) : "r"(a), "r"(one), "r"(b));
    return d;
}

// clip(floor(s), -128, 127) via saturating round-to-neg-inf conversion, then
// back to float. Bit-identical to clip(floor(s)*sigma, tmin, tmax)/sigma since
// sigma>0 is a power of two, tmin=-128*sigma, tmax=127*sigma.
__device__ __forceinline__ float floor_clip_s8(float s) {
    int   q;
    float r;
    asm("cvt.rmi.s8.f32 %0, %1;" : "=r"(q) : "f"(s));
    asm("cvt.rn.f32.s8 %0, %1;"  : "=f"(r) : "r"(q));
    return r;
}

__global__ void __launch_bounds__(256) quantize_kernel(const float* __restrict__ x,
                                                       float* __restrict__ out,
                                                       uint32_t k0, uint32_t k1,
                                                       uint32_t one, int n) {
    int t = blockIdx.x * blockDim.x + threadIdx.x;
    int j = t << 2;
    if (j >= n) return;

    const uint32_t ks2 = k0 ^ k1 ^ 0x1BD11BDAu;
    const uint32_t kc1 = ks2 + 1u;
    const uint32_t kc2 = k0  + 2u;
    const uint32_t kc3 = k1  + 3u;
    const uint32_t kc4 = ks2 + 4u;
    const uint32_t kc5 = k0  + 5u;
    // opaque 2^23 (runtime 'one' defeats folding) for the mulhi shift
    const uint32_t m23 = one << 23;

    float4 qp = g_qp;             // x=sigma, y=inv
    float4 v = *reinterpret_cast<const float4*>(x + j);
    float4 q;

    uint32_t x1b = addi((uint32_t)j, one, k1);   // j + k1

    // Round: IMAD add (fma) + SHF rotate (alu) + LOP3 xor (alu). Proven best.
#define TF_S(r) { x0 = addi(x0, one, x1); x1 = __funnelshift_l(x1, x1, (r)) ^ x0; }

#pragma unroll
    for (int c = 0; c < 4; c++) {
        // threefry2x32 block: key=(k0,k1), counter=(0, j+c)
        uint32_t x0 = k0;
        uint32_t x1 = x1b + (uint32_t)c;
        TF_S(13) TF_S(15) TF_S(26) TF_S(6)
        x0 = addi(x0, one, k1);  x1 = addi(x1, one, kc1);
        TF_S(17) TF_S(29) TF_S(16) TF_S(24)
        x0 = addi(x0, one, ks2); x1 = addi(x1, one, kc2);
        TF_S(13) TF_S(15) TF_S(26) TF_S(6)
        x0 = addi(x0, one, k0);  x1 = addi(x1, one, kc3);
        TF_S(17) TF_S(29) TF_S(16) TF_S(24)
        x0 = addi(x0, one, k1);  x1 = addi(x1, one, kc4);
        TF_S(13) TF_S(15) TF_S(26) TF_S(6)
        x0 = addi(x0, one, ks2); x1 = addi(x1, one, kc5);

        uint32_t bits = x0 ^ x1;
        // bits>>9 == mulhi(bits, 2^23): one narrow IMAD.HI on the fma pipe
        // instead of SHF on the saturated alu pipe.
        uint32_t hi;
        asm("mul.hi.u32 %0, %1, %2;" : "=r"(hi) : "r"(bits), "r"(m23));
        // u = float(hi)*2^-23 == bitcast(hi|0x3f800000)-1 exactly (hi < 2^23).
        float f = __uint2float_rn(hi);
        float a = (&v.x)[c];
        // s = a*inv + u (FFMA, bit-identical: u term is exact).
        float s  = __fmaf_rn(f, 1.1920928955078125e-7f, __fmul_rn(a, qp.y));
        // clip(floor(s),-128,127)*sigma == clip(floor(s)*sigma, tmin, tmax)
        (&q.x)[c] = __fmul_rn(floor_clip_s8(s), qp.x);
    }
#undef TF_S

    *reinterpret_cast<float4*>(out + j) = q;
}

// --- host-side threefry for key fold ---------------------------------------
static void h_threefry(uint32_t k0, uint32_t k1, uint32_t x0, uint32_t x1,
                       uint32_t& o0, uint32_t& o1) {
    auto rotl = [](uint32_t v, int r) { return (v << r) | (v >> (32 - r)); };
    uint32_t ks[3] = { k0, k1, k0 ^ k1 ^ 0x1BD11BDAu };
    const int R[2][4] = { {13, 15, 26, 6}, {17, 29, 16, 24} };
    x0 += ks[0]; x1 += ks[1];
    for (int i = 0; i < 5; i++) {
        for (int jj = 0; jj < 4; jj++) {
            x0 += x1; x1 = rotl(x1, R[i % 2][jj]); x1 ^= x0;
        }
        x0 += ks[(i + 1) % 3];
        x1 += ks[(i + 2) % 3] + (uint32_t)(i + 1);
    }
    o0 = x0; o1 = x1;
}

extern "C" void kernel_launch(void* const* d_in, const int* in_sizes, int n_in,
                              void* d_out, int out_size) {
    const float* x = (const float*)d_in[0];
    float* out = (float*)d_out;
    int n = in_sizes[0];           // 32*2048*2048 = 134217728

    // key = fold_in(key(42), 0): threefry_2x32(key=[0,42], count=[0,0])
    uint32_t fk0, fk1;
    h_threefry(0u, 42u, 0u, 0u, fk0, fk1);

    int nquads = n >> 2;
    count_decide_kernel<<<2048, 256>>>((const float4*)x, nquads, (float)n);

    int qthreads = (n + 3) >> 2;
    int qblocks = (qthreads + 255) / 256;
    quantize_kernel<<<qblocks, 256>>>(x, out, fk0, fk1, 1u, n);
}

// round 6
// speedup vs baseline: 1.0968x; 1.0058x over previous
#include <cuda_runtime.h>
#include <cstdint>

// ---------------------------------------------------------------------------
// DynamicFixedQuantizer, R6 (= R5 + 8-elem/thread quantize):
//  - count_decide fused kernel (2048 blocks) -> g_qp.
//  - quantize: 8 elements/thread (2x float4), 8 independent threefry chains
//    for ILP; rounds in IMAD(add)/SHF/LOP3 form; floor+clamp fused into
//    cvt.rmi.s8.f32; u-term fused into FFMA; bits>>9 as mulhi on fma pipe.
// ---------------------------------------------------------------------------

__device__ unsigned int g_over  = 0u;
__device__ unsigned int g_under = 0u;
__device__ unsigned int g_done  = 0u;
__device__ float4 g_qp;   // x=sigma, y=1/sigma

// Thresholds from sigma0 = 2^(6-8) = 0.25, bit=8, half=128:
#define T_MAX0   31.75f
#define T_MIN0  (-32.0f)
#define HT_MAX0  15.875f
#define HT_MIN0 (-16.0f)

__device__ __forceinline__ void count4(float4 v, int& over, int& under) {
    over  += (v.x > T_MAX0)  + (v.x < T_MIN0);
    under += (v.x > HT_MAX0) + (v.x < HT_MIN0);
    over  += (v.y > T_MAX0)  + (v.y < T_MIN0);
    under += (v.y > HT_MAX0) + (v.y < HT_MIN0);
    over  += (v.z > T_MAX0)  + (v.z < T_MIN0);
    under += (v.z > HT_MAX0) + (v.z < HT_MIN0);
    over  += (v.w > T_MAX0)  + (v.w < T_MIN0);
    under += (v.w > HT_MAX0) + (v.w < HT_MIN0);
}

__global__ void __launch_bounds__(256) count_decide_kernel(
        const float4* __restrict__ x4, int nquads, float n) {
    int tid    = blockIdx.x * blockDim.x + threadIdx.x;
    int stride = gridDim.x * blockDim.x;
    int over = 0, under = 0;

    int i = tid;
    for (; i + 3 * stride < nquads; i += 4 * stride) {
        float4 a = x4[i];
        float4 b = x4[i + stride];
        float4 c = x4[i + 2 * stride];
        float4 d = x4[i + 3 * stride];
        count4(a, over, under);
        count4(b, over, under);
        count4(c, over, under);
        count4(d, over, under);
    }
    for (; i < nquads; i += stride) {
        count4(x4[i], over, under);
    }

    over  = __reduce_add_sync(0xffffffffu, over);
    under = __reduce_add_sync(0xffffffffu, under);

    __shared__ int so[8], su[8];
    int warp = threadIdx.x >> 5;
    int lane = threadIdx.x & 31;
    if (lane == 0) { so[warp] = over; su[warp] = under; }
    __syncthreads();

    if (threadIdx.x == 0) {
        int o = 0, u = 0;
#pragma unroll
        for (int w = 0; w < 8; w++) { o += so[w]; u += su[w]; }
        atomicAdd(&g_over,  (unsigned)o);
        atomicAdd(&g_under, (unsigned)u);
        __threadfence();
        unsigned t = atomicAdd(&g_done, 1u);
        if (t == gridDim.x - 1) {
            unsigned ov = atomicAdd(&g_over,  0u);
            unsigned un = atomicAdd(&g_under, 0u);
            float overflow  = __uint2float_rn(ov) / n;
            float underflow = __uint2float_rn(un) / n;
            float sigma = 0.25f;
            if (overflow > 0.01f)       sigma = 0.5f;
            else if (underflow < 0.01f) sigma = 0.125f;
            g_qp = make_float4(sigma, 1.0f / sigma, 0.0f, 0.0f);
            atomicExch(&g_over,  0u);
            atomicExch(&g_under, 0u);
            __threadfence();
            atomicExch(&g_done,  0u);
        }
    }
}

// --- integer add forced onto the fma pipe: IMAD d = a*one + b ---------------
__device__ __forceinline__ uint32_t addi(uint32_t a, uint32_t one, uint32_t b) {
    uint32_t d;
    asm("mad.lo.u32 %0, %1, %2, %3;" : "=r"(d) : "r"(a), "r"(one), "r"(b));
    return d;
}

// clip(floor(s), -128, 127) via saturating round-to-neg-inf conversion, then
// back to float. Bit-identical to clip(floor(s)*sigma, tmin, tmax)/sigma since
// sigma>0 is a power of two, tmin=-128*sigma, tmax=127*sigma.
__device__ __forceinline__ float floor_clip_s8(float s) {
    int   q;
    float r;
    asm("cvt.rmi.s8.f32 %0, %1;" : "=r"(q) : "f"(s));
    asm("cvt.rn.f32.s8 %0, %1;"  : "=f"(r) : "r"(q));
    return r;
}

__global__ void __launch_bounds__(256) quantize_kernel(const float* __restrict__ x,
                                                       float* __restrict__ out,
                                                       uint32_t k0, uint32_t k1,
                                                       uint32_t one, int n) {
    int t = blockIdx.x * blockDim.x + threadIdx.x;
    int j = t << 3;                 // 8 elements per thread
    if (j >= n) return;

    const uint32_t ks2 = k0 ^ k1 ^ 0x1BD11BDAu;
    const uint32_t kc1 = ks2 + 1u;
    const uint32_t kc2 = k0  + 2u;
    const uint32_t kc3 = k1  + 3u;
    const uint32_t kc4 = ks2 + 4u;
    const uint32_t kc5 = k0  + 5u;
    const uint32_t m23 = one << 23;   // opaque 2^23 for the mulhi shift

    // Streaming loads: both float4s issued back-to-back (MLP=2).
    float4 v0 = __ldcg(reinterpret_cast<const float4*>(x + j));
    float4 v1 = __ldcg(reinterpret_cast<const float4*>(x + j + 4));

    uint32_t x1b = addi((uint32_t)j, one, k1);   // j + k1

    // Round: IMAD add (fma) + SHF rotate (alu) + LOP3 xor (alu). Proven best.
#define TF_S(r) { x0 = addi(x0, one, x1); x1 = __funnelshift_l(x1, x1, (r)) ^ x0; }

    float f[8];
#pragma unroll
    for (int c = 0; c < 8; c++) {
        // threefry2x32 block: key=(k0,k1), counter=(0, j+c)
        uint32_t x0 = k0;
        uint32_t x1 = x1b + (uint32_t)c;
        TF_S(13) TF_S(15) TF_S(26) TF_S(6)
        x0 = addi(x0, one, k1);  x1 = addi(x1, one, kc1);
        TF_S(17) TF_S(29) TF_S(16) TF_S(24)
        x0 = addi(x0, one, ks2); x1 = addi(x1, one, kc2);
        TF_S(13) TF_S(15) TF_S(26) TF_S(6)
        x0 = addi(x0, one, k0);  x1 = addi(x1, one, kc3);
        TF_S(17) TF_S(29) TF_S(16) TF_S(24)
        x0 = addi(x0, one, k1);  x1 = addi(x1, one, kc4);
        TF_S(13) TF_S(15) TF_S(26) TF_S(6)
        x0 = addi(x0, one, ks2); x1 = addi(x1, one, kc5);

        uint32_t bits = x0 ^ x1;
        // bits>>9 == mulhi(bits, 2^23): narrow IMAD.HI on the fma pipe.
        uint32_t hi;
        asm("mul.hi.u32 %0, %1, %2;" : "=r"(hi) : "r"(bits), "r"(m23));
        // u = float(hi)*2^-23 == bitcast(hi|0x3f800000)-1 exactly (hi < 2^23).
        f[c] = __uint2float_rn(hi);
    }
#undef TF_S

    float4 qp = g_qp;             // x=sigma, y=inv

    float4 q0, q1;
#pragma unroll
    for (int c = 0; c < 4; c++) {
        float a0 = (&v0.x)[c];
        float a1 = (&v1.x)[c];
        float s0 = __fmaf_rn(f[c],     1.1920928955078125e-7f, __fmul_rn(a0, qp.y));
        float s1 = __fmaf_rn(f[c + 4], 1.1920928955078125e-7f, __fmul_rn(a1, qp.y));
        (&q0.x)[c] = __fmul_rn(floor_clip_s8(s0), qp.x);
        (&q1.x)[c] = __fmul_rn(floor_clip_s8(s1), qp.x);
    }
    __stcs(reinterpret_cast<float4*>(out + j),     q0);
    __stcs(reinterpret_cast<float4*>(out + j + 4), q1);
}

// --- host-side threefry for key fold ---------------------------------------
static void h_threefry(uint32_t k0, uint32_t k1, uint32_t x0, uint32_t x1,
                       uint32_t& o0, uint32_t& o1) {
    auto rotl = [](uint32_t v, int r) { return (v << r) | (v >> (32 - r)); };
    uint32_t ks[3] = { k0, k1, k0 ^ k1 ^ 0x1BD11BDAu };
    const int R[2][4] = { {13, 15, 26, 6}, {17, 29, 16, 24} };
    x0 += ks[0]; x1 += ks[1];
    for (int i = 0; i < 5; i++) {
        for (int jj = 0; jj < 4; jj++) {
            x0 += x1; x1 = rotl(x1, R[i % 2][jj]); x1 ^= x0;
        }
        x0 += ks[(i + 1) % 3];
        x1 += ks[(i + 2) % 3] + (uint32_t)(i + 1);
    }
    o0 = x0; o1 = x1;
}

extern "C" void kernel_launch(void* const* d_in, const int* in_sizes, int n_in,
                              void* d_out, int out_size) {
    const float* x = (const float*)d_in[0];
    float* out = (float*)d_out;
    int n = in_sizes[0];           // 32*2048*2048 = 134217728

    // key = fold_in(key(42), 0): threefry_2x32(key=[0,42], count=[0,0])
    uint32_t fk0, fk1;
    h_threefry(0u, 42u, 0u, 0u, fk0, fk1);

    int nquads = n >> 2;
    count_decide_kernel<<<2048, 256>>>((const float4*)x, nquads, (float)n);

    int qthreads = (n + 7) >> 3;   // 8 elements per thread
    int qblocks = (qthreads + 255) / 256;
    quantize_kernel<<<qblocks, 256>>>(x, out, fk0, fk1, 1u, n);
}